// round 3
// baseline (speedup 1.0000x reference)
#include <cuda_runtime.h>
#include <math.h>

// Problem constants
#define NN 4            // batch per stream
#define CC 256          // channels
#define TT 400          // time
#define VV 25           // joints
#define SS 3            // heads
#define CIc 64          // inner channels
#define TVc (TT*VV)     // 10000
#define CTVc (CC*TVc)   // 2,560,000
#define QKCc (2*SS*CIc) // 384
#define SCc (SS*CC)     // 768

// ---------------- scratch (static device globals; no allocation) ----------------
__device__ __align__(16) float g_y  [NN*CTVc];        // x+pe / temporal input+pe
__device__ __align__(16) float g_qk [NN*QKCc*TVc];    // in-conv output
__device__ __align__(16) float g_atts[NN*SS*VV*VV];   // spatial attention
__device__ __align__(16) float g_attt[(long)NN*SS*TT*TT]; // temporal attention
__device__ __align__(16) float g_z  [NN*SCc*TVc];     // z (spatial) / z2T (temporal, v-major)
__device__ __align__(16) float g_h  [NN*CTVc];        // spatial hidden
__device__ __align__(16) float g_s  [NN*CTVc];        // spatial output (temporal input)
__device__ __align__(16) float g_sT [NN*CTVc];        // temporal input, v-major [n][v][c][t]
__device__ __align__(16) float g_hT [NN*CTVc];        // temporal hidden, v-major
__device__ __align__(16) float g_oT [NN*CTVc];        // temporal output, v-major

// ---------------- elementwise: out = in + pe (broadcast over batch) ----------------
__global__ __launch_bounds__(256) void add_pe_kernel(
    const float4* __restrict__ in, const float4* __restrict__ pe, float4* __restrict__ out)
{
    int i = blockIdx.x * 256 + threadIdx.x;
    const int total4 = NN * CTVc / 4;
    if (i >= total4) return;
    int pei = i % (CTVc / 4);
    float4 a = in[i], b = pe[pei];
    float4 r; r.x = a.x + b.x; r.y = a.y + b.y; r.z = a.z + b.z; r.w = a.w + b.w;
    out[i] = r;
}

// ---------------- generic batched GEMM: C[b] = A (M x K) * B[b] (K x P) ----------------
// EPI==0: C = acc + bias
// EPI==1: C = lrelu(res + (acc + bias)*gamma + beta)
template<int EPI>
__global__ __launch_bounds__(256) void gemm64(
    const float* __restrict__ A, const float* __restrict__ B, float* __restrict__ Cout,
    const float* __restrict__ bias, const float* __restrict__ gam, const float* __restrict__ bet,
    const float* __restrict__ res, int M, int K, int P, long sB, long sC)
{
    __shared__ float As[16][65];
    __shared__ float Bs[16][64];
    int b  = blockIdx.z;
    const float* Bb = B + (long)b * sB;
    int p0 = blockIdx.x * 64, m0 = blockIdx.y * 64;
    int tid = threadIdx.x;
    int tx = tid & 15, ty = tid >> 4;
    float acc[4][4];
#pragma unroll
    for (int i = 0; i < 4; i++)
#pragma unroll
        for (int j = 0; j < 4; j++) acc[i][j] = 0.f;

    for (int k0 = 0; k0 < K; k0 += 16) {
#pragma unroll
        for (int i = 0; i < 4; i++) {
            int li = tid + 256 * i;
            int mm = li >> 4, kk = li & 15;
            As[kk][mm] = A[(long)(m0 + mm) * K + (k0 + kk)];   // M always %64==0
        }
#pragma unroll
        for (int i = 0; i < 4; i++) {
            int li = tid + 256 * i;
            int kk = li >> 6, pp = li & 63;
            int p = p0 + pp;
            Bs[kk][pp] = (p < P) ? Bb[(long)(k0 + kk) * P + p] : 0.f;
        }
        __syncthreads();
#pragma unroll
        for (int kk = 0; kk < 16; kk++) {
            float a[4], bb[4];
#pragma unroll
            for (int i = 0; i < 4; i++) a[i] = As[kk][ty * 4 + i];
#pragma unroll
            for (int j = 0; j < 4; j++) bb[j] = Bs[kk][tx * 4 + j];
#pragma unroll
            for (int i = 0; i < 4; i++)
#pragma unroll
                for (int j = 0; j < 4; j++) acc[i][j] += a[i] * bb[j];
        }
        __syncthreads();
    }

#pragma unroll
    for (int i = 0; i < 4; i++) {
        int m = m0 + ty * 4 + i;
        float bi = bias[m];
        float gm = 0.f, bt = 0.f;
        if (EPI) { gm = gam[m]; bt = bet[m]; }
#pragma unroll
        for (int j = 0; j < 4; j++) {
            int p = p0 + tx * 4 + j;
            if (p < P) {
                long off = (long)b * sC + (long)m * P + p;
                float v = acc[i][j] + bi;
                if (EPI) {
                    v = v * gm + bt + res[off];
                    v = (v >= 0.f) ? v : 0.1f * v;
                }
                Cout[off] = v;
            }
        }
    }
}

// ---------------- spatial attention: att[n,s,u,v] = tanh(sum_{c,t} q*k /(CI*T))*alpha + att0 ----------------
// one block per (n,s,u); qk layout [(n*384+ch)][t][v], channel slabs contiguous.
__global__ __launch_bounds__(256) void atts_kernel(
    const float* __restrict__ alphas, const float* __restrict__ att0)
{
    int u = blockIdx.x % VV;
    int s = (blockIdx.x / VV) % SS;
    int n = blockIdx.x / (VV * SS);
    const float* qb = g_qk + ((long)n * QKCc + s * CIc) * TVc;
    const float* kb = g_qk + ((long)n * QKCc + (SS + s) * CIc) * TVc;
    float acc[VV];
#pragma unroll
    for (int v = 0; v < VV; v++) acc[v] = 0.f;
    int tid = threadIdx.x;
    for (int it = tid; it < CIc * TT; it += 256) {       // it = c*T + t; offset = it*V
        long base = (long)it * VV;
        float qv = qb[base + u];
#pragma unroll
        for (int v = 0; v < VV; v++) acc[v] += qv * kb[base + v];
    }
    __shared__ float sred[VV][256];
#pragma unroll
    for (int v = 0; v < VV; v++) sred[v][tid] = acc[v];
    __syncthreads();
    for (int st = 128; st > 0; st >>= 1) {
        if (tid < st) {
#pragma unroll
            for (int v = 0; v < VV; v++) sred[v][tid] += sred[v][tid + st];
        }
        __syncthreads();
    }
    if (tid < VV) {
        float val = tanhf(sred[tid][0] * (1.f / (CIc * TT))) * alphas[s]
                  + att0[(s * VV + u) * VV + tid];
        g_atts[((n * SS + s) * VV + u) * VV + tid] = val;
    }
}

// ---------------- spatial apply: z[n, s*C+c, t, w] = sum_v x[n,c,t,v] * att[n,s,v,w] ----------------
__global__ __launch_bounds__(256) void zspat_kernel(const float* __restrict__ x)
{
    int n = blockIdx.y;
    __shared__ float att[SS * VV * VV];
    for (int i = threadIdx.x; i < SS * VV * VV; i += 256) att[i] = g_atts[n * SS * VV * VV + i];
    __syncthreads();
    int row = blockIdx.x * 256 + threadIdx.x;  // over C*T
    if (row >= CC * TT) return;
    int c = row / TT, t = row % TT;
    const float* xr = x + (long)n * CTVc + (long)row * VV;
    float xv[VV];
#pragma unroll
    for (int v = 0; v < VV; v++) xv[v] = xr[v];
#pragma unroll
    for (int s = 0; s < SS; s++) {
        float outv[VV];
#pragma unroll
        for (int w = 0; w < VV; w++) outv[w] = 0.f;
#pragma unroll
        for (int v = 0; v < VV; v++) {
            float xx = xv[v];
            const float* ar = &att[(s * VV + v) * VV];
#pragma unroll
            for (int w = 0; w < VV; w++) outv[w] += xx * ar[w];
        }
        float* zr = g_z + ((long)(n * SCc + s * CC + c)) * TVc + (long)t * VV;
#pragma unroll
        for (int w = 0; w < VV; w++) zr[w] = outv[w];
    }
}

// ---------------- temporal attention: att[n,s,t,q] = tanh(sum_{c,v} q[c,t,v]k[c,q,v]/(CI*V))*alpha + att0t ----------------
// 64x64 output tile, K processed in c-chunks of 25 (one channel), contiguous loads.
__global__ __launch_bounds__(256) void attt_kernel(
    const float* __restrict__ alphat, const float* __restrict__ att0t)
{
    int ns = blockIdx.z; int n = ns / SS, s = ns % SS;
    int t0 = blockIdx.y * 64, q0 = blockIdx.x * 64;
    const float* qb = g_qk + ((long)n * QKCc + s * CIc) * TVc;
    const float* kb = g_qk + ((long)n * QKCc + (SS + s) * CIc) * TVc;
    __shared__ float Qs[VV][65], Ks[VV][65];
    int tid = threadIdx.x, tx = tid & 15, ty = tid >> 4;
    float acc[4][4];
#pragma unroll
    for (int i = 0; i < 4; i++)
#pragma unroll
        for (int j = 0; j < 4; j++) acc[i][j] = 0.f;

    for (int c = 0; c < CIc; c++) {
        const float* qsrc = qb + (long)c * TVc;
        const float* ksrc = kb + (long)c * TVc;
        for (int li = tid; li < 64 * VV; li += 256) {   // li = tt*25 + v, contiguous
            int ttl = li / VV, v = li % VV;
            float qv = 0.f, kv = 0.f;
            if (t0 + ttl < TT) qv = qsrc[t0 * VV + li];
            if (q0 + ttl < TT) kv = ksrc[q0 * VV + li];
            Qs[v][ttl] = qv; Ks[v][ttl] = kv;
        }
        __syncthreads();
#pragma unroll
        for (int v = 0; v < VV; v++) {
            float a[4], bb[4];
#pragma unroll
            for (int i = 0; i < 4; i++) a[i] = Qs[v][ty * 4 + i];
#pragma unroll
            for (int j = 0; j < 4; j++) bb[j] = Ks[v][tx * 4 + j];
#pragma unroll
            for (int i = 0; i < 4; i++)
#pragma unroll
                for (int j = 0; j < 4; j++) acc[i][j] += a[i] * bb[j];
        }
        __syncthreads();
    }
    float al = alphat[s];
#pragma unroll
    for (int i = 0; i < 4; i++)
#pragma unroll
        for (int j = 0; j < 4; j++) {
            int t = t0 + ty * 4 + i, q = q0 + tx * 4 + j;
            if (t < TT && q < TT) {
                float val = tanhf(acc[i][j] * (1.f / (CIc * VV))) * al
                          + att0t[((long)s * TT + t) * TT + q];
                g_attt[(((long)(n * SS + s)) * TT + t) * TT + q] = val;
            }
        }
}

// ---------------- transpose to v-major: out[n][v][c][t] = in[n][c][t][v] ----------------
__global__ __launch_bounds__(256) void tr_vmajor_kernel(
    const float* __restrict__ in, float* __restrict__ out)
{
    __shared__ float sh[VV][33];
    int n = blockIdx.z, c = blockIdx.y, t0 = blockIdx.x * 32;
    int nmax = min(32, TT - t0);
    const float* src = in + ((long)(n * CC + c) * TT + t0) * VV;
    for (int li = threadIdx.x; li < nmax * VV; li += 256) {
        int t = li / VV, v = li % VV;
        sh[v][t] = src[li];
    }
    __syncthreads();
    for (int li = threadIdx.x; li < VV * 32; li += 256) {
        int v = li >> 5, t = li & 31;
        if (t < nmax)
            out[((long)(n * VV + v) * CC + c) * TT + t0 + t] = sh[v][t];
    }
}

// ---------------- final store: out[n][c][q][v] = inT[n][v][c][q] ----------------
__global__ __launch_bounds__(256) void store_out_kernel(
    const float* __restrict__ inT, float* __restrict__ out)
{
    __shared__ float sh[VV][33];
    int n = blockIdx.z, c = blockIdx.y, q0 = blockIdx.x * 32;
    int nmax = min(32, TT - q0);
    for (int li = threadIdx.x; li < VV * 32; li += 256) {
        int v = li >> 5, q = li & 31;
        if (q < nmax)
            sh[v][q] = inT[((long)(n * VV + v) * CC + c) * TT + q0 + q];
    }
    __syncthreads();
    float* dst = out + ((long)(n * CC + c) * TT + q0) * VV;
    for (int li = threadIdx.x; li < nmax * VV; li += 256) {
        int q = li / VV, v = li % VV;
        dst[li] = sh[v][q];
    }
}

// ---------------- temporal apply: z2T[(n,v)][s*C+c][q] = sum_t sT[(n,v)][c][t] * attt[(n,s)][t][q] ----------------
__global__ __launch_bounds__(256) void ztemp_kernel()
{
    int bz = blockIdx.z;
    int v = bz % VV, s = (bz / VV) % SS, n = bz / (VV * SS);
    const float* A = g_sT + (long)(n * VV + v) * CC * TT;            // [256][400]
    const float* B = g_attt + (long)(n * SS + s) * TT * TT;          // [400][400]
    float* Cc = g_z + ((long)((n * VV + v) * SCc) + s * CC) * TT;    // [256][400]
    int p0 = blockIdx.x * 64, m0 = blockIdx.y * 64;
    __shared__ float As[16][65];
    __shared__ float Bs[16][64];
    int tid = threadIdx.x, tx = tid & 15, ty = tid >> 4;
    float acc[4][4];
#pragma unroll
    for (int i = 0; i < 4; i++)
#pragma unroll
        for (int j = 0; j < 4; j++) acc[i][j] = 0.f;

    for (int k0 = 0; k0 < TT; k0 += 16) {
#pragma unroll
        for (int i = 0; i < 4; i++) {
            int li = tid + 256 * i;
            int mm = li >> 4, kk = li & 15;
            As[kk][mm] = A[(long)(m0 + mm) * TT + k0 + kk];
        }
#pragma unroll
        for (int i = 0; i < 4; i++) {
            int li = tid + 256 * i;
            int kk = li >> 6, pp = li & 63;
            int p = p0 + pp;
            Bs[kk][pp] = (p < TT) ? B[(long)(k0 + kk) * TT + p] : 0.f;
        }
        __syncthreads();
#pragma unroll
        for (int kk = 0; kk < 16; kk++) {
            float a[4], bb[4];
#pragma unroll
            for (int i = 0; i < 4; i++) a[i] = As[kk][ty * 4 + i];
#pragma unroll
            for (int j = 0; j < 4; j++) bb[j] = Bs[kk][tx * 4 + j];
#pragma unroll
            for (int i = 0; i < 4; i++)
#pragma unroll
                for (int j = 0; j < 4; j++) acc[i][j] += a[i] * bb[j];
        }
        __syncthreads();
    }
#pragma unroll
    for (int i = 0; i < 4; i++) {
        int m = m0 + ty * 4 + i;
#pragma unroll
        for (int j = 0; j < 4; j++) {
            int p = p0 + tx * 4 + j;
            if (p < TT) Cc[(long)m * TT + p] = acc[i][j];
        }
    }
}

// ---------------- host orchestration ----------------
static void run_stream(const float* xin, float* outp,
    const float* pe_s, const float* pe_t,
    const float* insW, const float* insB, const float* alphas, const float* att0s,
    const float* outsW, const float* outsB, const float* outsG, const float* outsBe,
    const float* ffsW, const float* ffsB, const float* ffsG, const float* ffsBe,
    const float* intW, const float* intB, const float* alphat, const float* att0t,
    const float* outtW, const float* outtB, const float* outtG, const float* outtBe,
    const float* fftW, const float* fftB, const float* fftG, const float* fftBe,
    float* py, float* pqk, float* pz, float* ph, float* ps, float* psT, float* phT, float* poT)
{
    const int addBlocks = (NN * CTVc / 4 + 255) / 256;

    // ===== spatial =====
    add_pe_kernel<<<addBlocks, 256>>>((const float4*)xin, (const float4*)pe_s, (float4*)py);
    gemm64<0><<<dim3(157, QKCc / 64, NN), 256>>>(insW, py, pqk, insB, nullptr, nullptr, nullptr,
                                                 QKCc, CC, TVc, (long)CTVc, (long)QKCc * TVc);
    atts_kernel<<<NN * SS * VV, 256>>>(alphas, att0s);
    zspat_kernel<<<dim3((CC * TT + 255) / 256, NN), 256>>>(xin);
    gemm64<1><<<dim3(157, CC / 64, NN), 256>>>(outsW, pz, ph, outsB, outsG, outsBe, xin,
                                               CC, SCc, TVc, (long)SCc * TVc, (long)CTVc);
    gemm64<1><<<dim3(157, CC / 64, NN), 256>>>(ffsW, ph, ps, ffsB, ffsG, ffsBe, xin,
                                               CC, CC, TVc, (long)CTVc, (long)CTVc);

    // ===== temporal =====
    add_pe_kernel<<<addBlocks, 256>>>((const float4*)ps, (const float4*)pe_t, (float4*)py);
    gemm64<0><<<dim3(157, QKCc / 64, NN), 256>>>(intW, py, pqk, intB, nullptr, nullptr, nullptr,
                                                 QKCc, CC, TVc, (long)CTVc, (long)QKCc * TVc);
    attt_kernel<<<dim3(7, 7, NN * SS), 256>>>(alphat, att0t);
    tr_vmajor_kernel<<<dim3(13, CC, NN), 256>>>(ps, psT);
    ztemp_kernel<<<dim3(7, CC / 64, NN * SS * VV), 256>>>();
    gemm64<1><<<dim3(7, CC / 64, NN * VV), 256>>>(outtW, pz, phT, outtB, outtG, outtBe, psT,
                                                  CC, SCc, TT, (long)SCc * TT, (long)CC * TT);
    gemm64<1><<<dim3(7, CC / 64, NN * VV), 256>>>(fftW, phT, poT, fftB, fftG, fftBe, psT,
                                                  CC, CC, TT, (long)CC * TT, (long)CC * TT);
    store_out_kernel<<<dim3(13, CC, NN), 256>>>(poT, outp);
}

extern "C" void kernel_launch(void* const* d_in, const int* in_sizes, int n_in,
                              void* d_out, int out_size)
{
    const float* x      = (const float*)d_in[0];
    const float* x1     = (const float*)d_in[1];
    const float* pe_s   = (const float*)d_in[2];
    const float* pe_t   = (const float*)d_in[3];
    const float* insW   = (const float*)d_in[4];
    const float* insB   = (const float*)d_in[5];
    const float* alphas = (const float*)d_in[6];
    const float* att0s  = (const float*)d_in[7];
    const float* outsW  = (const float*)d_in[8];
    const float* outsB  = (const float*)d_in[9];
    const float* outsG  = (const float*)d_in[10];
    const float* outsBe = (const float*)d_in[11];
    const float* ffsW   = (const float*)d_in[12];
    const float* ffsB   = (const float*)d_in[13];
    const float* ffsG   = (const float*)d_in[14];
    const float* ffsBe  = (const float*)d_in[15];
    const float* intW   = (const float*)d_in[16];
    const float* intB   = (const float*)d_in[17];
    const float* alphat = (const float*)d_in[18];
    const float* att0t  = (const float*)d_in[19];
    const float* outtW  = (const float*)d_in[20];
    const float* outtB  = (const float*)d_in[21];
    const float* outtG  = (const float*)d_in[22];
    const float* outtBe = (const float*)d_in[23];
    const float* fftW   = (const float*)d_in[24];
    const float* fftB   = (const float*)d_in[25];
    const float* fftG   = (const float*)d_in[26];
    const float* fftBe  = (const float*)d_in[27];
    // d_in[28] = case (unused by the reference computation)

    float *py, *pqk, *pz, *ph, *ps, *psT, *phT, *poT;
    cudaGetSymbolAddress((void**)&py,  g_y);
    cudaGetSymbolAddress((void**)&pqk, g_qk);
    cudaGetSymbolAddress((void**)&pz,  g_z);
    cudaGetSymbolAddress((void**)&ph,  g_h);
    cudaGetSymbolAddress((void**)&ps,  g_s);
    cudaGetSymbolAddress((void**)&psT, g_sT);
    cudaGetSymbolAddress((void**)&phT, g_hT);
    cudaGetSymbolAddress((void**)&poT, g_oT);

    float* out = (float*)d_out;

    run_stream(x,  out,
               pe_s, pe_t, insW, insB, alphas, att0s, outsW, outsB, outsG, outsBe,
               ffsW, ffsB, ffsG, ffsBe, intW, intB, alphat, att0t,
               outtW, outtB, outtG, outtBe, fftW, fftB, fftG, fftBe,
               py, pqk, pz, ph, ps, psT, phT, poT);

    run_stream(x1, out + (long)NN * CTVc,
               pe_s, pe_t, insW, insB, alphas, att0s, outsW, outsB, outsG, outsBe,
               ffsW, ffsB, ffsG, ffsBe, intW, intB, alphat, att0t,
               outtW, outtB, outtG, outtBe, fftW, fftB, fftG, fftBe,
               py, pqk, pz, ph, ps, psT, phT, poT);
}

// round 4
// speedup vs baseline: 1.9317x; 1.9317x over previous
#include <cuda_runtime.h>
#include <math.h>
#include <stdint.h>

// Problem constants
#define NN 4            // batch per stream
#define CC 256          // channels
#define TT 400          // time
#define VV 25           // joints
#define SS 3            // heads
#define CIc 64          // inner channels
#define TVc (TT*VV)     // 10000
#define CTVc (CC*TVc)   // 2,560,000
#define QKCc (2*SS*CIc) // 384
#define SCc (SS*CC)     // 768

#define BK 16
#define BMp 136   // 128 + 8 : row stride ≡ 8 (mod 32) -> conflict-free tf32 frag loads
#define BNp 72    // 64 + 8

// ---------------- scratch (static device globals; no allocation) ----------------
__device__ __align__(16) float g_y  [NN*CTVc];
__device__ __align__(16) float g_qk [NN*QKCc*TVc];
__device__ __align__(16) float g_atts[NN*SS*VV*VV];
__device__ __align__(16) float g_attt[(long)NN*SS*TT*TT];
__device__ __align__(16) float g_z  [NN*SCc*TVc];
__device__ __align__(16) float g_h  [NN*CTVc];
__device__ __align__(16) float g_s  [NN*CTVc];
__device__ __align__(16) float g_sT [NN*CTVc];   // [n][v][c][t]
__device__ __align__(16) float g_sTk[NN*CTVc];   // [n][v][t][c]  (k-major A for ztemp)
__device__ __align__(16) float g_hT [NN*CTVc];
__device__ __align__(16) float g_oT [NN*CTVc];
__device__ __align__(16) float g_wt [6][768*256]; // k-major weight copies

// ---------------- helpers ----------------
__device__ __forceinline__ float t32(float x) {
    uint32_t u; asm("cvt.rna.tf32.f32 %0, %1;" : "=r"(u) : "f"(x));
    return __uint_as_float(u);
}

__device__ __forceinline__ void mma8(float* c, const uint32_t* a, const uint32_t* b) {
    asm volatile(
      "mma.sync.aligned.m16n8k8.row.col.f32.tf32.tf32.f32 "
      "{%0,%1,%2,%3}, {%4,%5,%6,%7}, {%8,%9}, {%0,%1,%2,%3};\n"
      : "+f"(c[0]), "+f"(c[1]), "+f"(c[2]), "+f"(c[3])
      : "r"(a[0]), "r"(a[1]), "r"(a[2]), "r"(a[3]), "r"(b[0]), "r"(b[1]));
}

// ---------------- tf32 tensor-core GEMM tile body ----------------
// C[M,P] = At^T (At is K x M, k-major) * B (K x P, row-major)
// EPI 0: C = acc + bias ; EPI 1: C = lrelu(res + (acc+bias)*gam + bet) ; EPI 2: C = acc
template<int EPI>
__device__ __forceinline__ void gemm_tc_body(
    const float* __restrict__ At, const float* __restrict__ B,
    float* __restrict__ C, const float* __restrict__ res,
    const float* __restrict__ bias, const float* __restrict__ gam, const float* __restrict__ bet,
    int M, int K, int P)
{
    __shared__ float As[BK][BMp];
    __shared__ float Bs[BK][BNp];
    const int m0 = blockIdx.y * 128;
    const int p0 = blockIdx.x * 64;
    const int tid = threadIdx.x;
    const int lane = tid & 31, warp = tid >> 5;
    const int g = lane >> 2, q4 = lane & 3;
    const int mbase = (warp >> 1) * 32;   // 4 warps along M
    const int nbase = (warp & 1) * 32;    // 2 warps along N

    float c[2][4][4];
#pragma unroll
    for (int mt = 0; mt < 2; mt++)
#pragma unroll
        for (int nt = 0; nt < 4; nt++)
#pragma unroll
            for (int k = 0; k < 4; k++) c[mt][nt][k] = 0.f;

    // staging indices
    const int akk = tid >> 5;          // 0..7 (rows akk, akk+8)
    const int amg = (tid & 31) * 4;    // m within 128
    const int bkk = tid >> 4;          // 0..15
    const int bpg = (tid & 15) * 4;    // p within 64

    float4 ra0, ra1, rb0;

    auto loadg = [&](int k0) {
        const float* Ap = At + (long)(k0 + akk) * M + m0 + amg;
        ra0 = *(const float4*)Ap;
        ra1 = *(const float4*)(Ap + 8L * M);
        int p = p0 + bpg;
        if (p < P) rb0 = *(const float4*)(B + (long)(k0 + bkk) * P + p);
        else       rb0 = make_float4(0.f, 0.f, 0.f, 0.f);
    };
    auto stage = [&]() {
        float4 ca0 = make_float4(t32(ra0.x), t32(ra0.y), t32(ra0.z), t32(ra0.w));
        float4 ca1 = make_float4(t32(ra1.x), t32(ra1.y), t32(ra1.z), t32(ra1.w));
        float4 cb  = make_float4(t32(rb0.x), t32(rb0.y), t32(rb0.z), t32(rb0.w));
        *(float4*)&As[akk    ][amg] = ca0;
        *(float4*)&As[akk + 8][amg] = ca1;
        *(float4*)&Bs[bkk][bpg] = cb;
    };
    auto compute = [&]() {
#pragma unroll
        for (int k8 = 0; k8 < BK; k8 += 8) {
            uint32_t a[2][4], b[4][2];
#pragma unroll
            for (int mt = 0; mt < 2; mt++) {
                int mr = mbase + mt * 16 + g;
                a[mt][0] = __float_as_uint(As[k8 + q4    ][mr    ]);
                a[mt][1] = __float_as_uint(As[k8 + q4    ][mr + 8]);
                a[mt][2] = __float_as_uint(As[k8 + q4 + 4][mr    ]);
                a[mt][3] = __float_as_uint(As[k8 + q4 + 4][mr + 8]);
            }
#pragma unroll
            for (int nt = 0; nt < 4; nt++) {
                int nc = nbase + nt * 8 + g;
                b[nt][0] = __float_as_uint(Bs[k8 + q4    ][nc]);
                b[nt][1] = __float_as_uint(Bs[k8 + q4 + 4][nc]);
            }
#pragma unroll
            for (int mt = 0; mt < 2; mt++)
#pragma unroll
                for (int nt = 0; nt < 4; nt++)
                    mma8(c[mt][nt], a[mt], b[nt]);
        }
    };

    loadg(0);
    stage();
    __syncthreads();
    for (int k0 = BK; k0 < K; k0 += BK) {
        loadg(k0);      // global loads in flight during compute
        compute();
        __syncthreads();
        stage();
        __syncthreads();
    }
    compute();

    // epilogue
#pragma unroll
    for (int mt = 0; mt < 2; mt++) {
#pragma unroll
        for (int half = 0; half < 2; half++) {
            int r = m0 + mbase + mt * 16 + g + half * 8;
            float bi = 0.f, gm = 0.f, bt = 0.f;
            if (EPI < 2) bi = bias[r];
            if (EPI == 1) { gm = gam[r]; bt = bet[r]; }
#pragma unroll
            for (int nt = 0; nt < 4; nt++) {
                int pc = p0 + nbase + nt * 8 + q4 * 2;
                if (pc < P) {  // P even, pc even -> pc+1 < P
                    long off = (long)r * P + pc;
                    float v0 = c[mt][nt][half * 2 + 0];
                    float v1 = c[mt][nt][half * 2 + 1];
                    if (EPI == 0) { v0 += bi; v1 += bi; }
                    if (EPI == 1) {
                        v0 = (v0 + bi) * gm + bt + res[off];
                        v1 = (v1 + bi) * gm + bt + res[off + 1];
                        v0 = (v0 >= 0.f) ? v0 : 0.1f * v0;
                        v1 = (v1 >= 0.f) ? v1 : 0.1f * v1;
                    }
                    C[off] = v0; C[off + 1] = v1;
                }
            }
        }
    }
}

template<int EPI>
__global__ __launch_bounds__(256, 2) void gemm_tc(
    const float* __restrict__ At, const float* __restrict__ B, float* __restrict__ C,
    const float* __restrict__ res,
    const float* __restrict__ bias, const float* __restrict__ gam, const float* __restrict__ bet,
    int M, int K, int P, long sB, long sC)
{
    long z = blockIdx.z;
    gemm_tc_body<EPI>(At, B + z * sB, C + z * sC,
                      (EPI == 1) ? res + z * sC : res, bias, gam, bet, M, K, P);
}

// temporal apply: z2T[(n,v)][s*C+c][q] = sum_t sTk[(n,v)][t][c] * attt[(n,s)][t][q]
__global__ __launch_bounds__(256, 2) void ztemp_tc()
{
    int z = blockIdx.z;
    int v = z % VV, s = (z / VV) % SS, n = z / (VV * SS);
    const float* At = g_sTk + (long)(n * VV + v) * TT * CC;         // 400 x 256, k-major
    const float* B  = g_attt + (long)(n * SS + s) * TT * TT;        // 400 x 400
    float* C = g_z + ((long)(n * VV + v) * SCc + s * CC) * TT;      // 256 x 400
    gemm_tc_body<2>(At, B, C, nullptr, nullptr, nullptr, nullptr, CC, TT, TT);
}

// ---------------- batched 2D transpose: out[z][k][m] = in[z][m][k] ----------------
__global__ __launch_bounds__(256) void transpose_b(
    const float* __restrict__ in, float* __restrict__ out,
    int M, int K, long sin, long sout)
{
    __shared__ float sh[32][33];
    const float* ip = in + (long)blockIdx.z * sin;
    float* op = out + (long)blockIdx.z * sout;
    int k0 = blockIdx.x * 32, m0 = blockIdx.y * 32;
    int tx = threadIdx.x & 31, ty = threadIdx.x >> 5;
    for (int i = ty; i < 32; i += 8) {
        int m = m0 + i, k = k0 + tx;
        if (m < M && k < K) sh[i][tx] = ip[(long)m * K + k];
    }
    __syncthreads();
    for (int i = ty; i < 32; i += 8) {
        int k = k0 + i, m = m0 + tx;
        if (k < K && m < M) op[(long)k * M + m] = sh[tx][i];
    }
}

// ---------------- elementwise add pe ----------------
__global__ __launch_bounds__(256) void add_pe_kernel(
    const float4* __restrict__ in, const float4* __restrict__ pe, float4* __restrict__ out)
{
    int i = blockIdx.x * 256 + threadIdx.x;
    const int total4 = NN * CTVc / 4;
    if (i >= total4) return;
    int pei = i % (CTVc / 4);
    float4 a = in[i], b = pe[pei];
    float4 r; r.x = a.x + b.x; r.y = a.y + b.y; r.z = a.z + b.z; r.w = a.w + b.w;
    out[i] = r;
}

// ---------------- spatial attention ----------------
__global__ __launch_bounds__(256) void atts_kernel(
    const float* __restrict__ alphas, const float* __restrict__ att0)
{
    int u = blockIdx.x % VV;
    int s = (blockIdx.x / VV) % SS;
    int n = blockIdx.x / (VV * SS);
    const float* qb = g_qk + ((long)n * QKCc + s * CIc) * TVc;
    const float* kb = g_qk + ((long)n * QKCc + (SS + s) * CIc) * TVc;
    float acc[VV];
#pragma unroll
    for (int v = 0; v < VV; v++) acc[v] = 0.f;
    int tid = threadIdx.x;
    for (int it = tid; it < CIc * TT; it += 256) {
        long base = (long)it * VV;
        float qv = qb[base + u];
#pragma unroll
        for (int v = 0; v < VV; v++) acc[v] += qv * kb[base + v];
    }
    __shared__ float sred[VV][256];
#pragma unroll
    for (int v = 0; v < VV; v++) sred[v][tid] = acc[v];
    __syncthreads();
    for (int st = 128; st > 0; st >>= 1) {
        if (tid < st) {
#pragma unroll
            for (int v = 0; v < VV; v++) sred[v][tid] += sred[v][tid + st];
        }
        __syncthreads();
    }
    if (tid < VV) {
        float val = tanhf(sred[tid][0] * (1.f / (CIc * TT))) * alphas[s]
                  + att0[(s * VV + u) * VV + tid];
        g_atts[((n * SS + s) * VV + u) * VV + tid] = val;
    }
}

// ---------------- spatial apply ----------------
__global__ __launch_bounds__(256) void zspat_kernel(const float* __restrict__ x)
{
    int n = blockIdx.y;
    __shared__ float att[SS * VV * VV];
    for (int i = threadIdx.x; i < SS * VV * VV; i += 256) att[i] = g_atts[n * SS * VV * VV + i];
    __syncthreads();
    int row = blockIdx.x * 256 + threadIdx.x;
    if (row >= CC * TT) return;
    int c = row / TT, t = row % TT;
    const float* xr = x + (long)n * CTVc + (long)row * VV;
    float xv[VV];
#pragma unroll
    for (int v = 0; v < VV; v++) xv[v] = xr[v];
#pragma unroll
    for (int s = 0; s < SS; s++) {
        float outv[VV];
#pragma unroll
        for (int w = 0; w < VV; w++) outv[w] = 0.f;
#pragma unroll
        for (int v = 0; v < VV; v++) {
            float xx = xv[v];
            const float* ar = &att[(s * VV + v) * VV];
#pragma unroll
            for (int w = 0; w < VV; w++) outv[w] += xx * ar[w];
        }
        float* zr = g_z + ((long)(n * SCc + s * CC + c)) * TVc + (long)t * VV;
#pragma unroll
        for (int w = 0; w < VV; w++) zr[w] = outv[w];
    }
}

// ---------------- temporal attention (FFMA, unchanged) ----------------
__global__ __launch_bounds__(256) void attt_kernel(
    const float* __restrict__ alphat, const float* __restrict__ att0t)
{
    int ns = blockIdx.z; int n = ns / SS, s = ns % SS;
    int t0 = blockIdx.y * 64, q0 = blockIdx.x * 64;
    const float* qb = g_qk + ((long)n * QKCc + s * CIc) * TVc;
    const float* kb = g_qk + ((long)n * QKCc + (SS + s) * CIc) * TVc;
    __shared__ float Qs[VV][65], Ks[VV][65];
    int tid = threadIdx.x, tx = tid & 15, ty = tid >> 4;
    float acc[4][4];
#pragma unroll
    for (int i = 0; i < 4; i++)
#pragma unroll
        for (int j = 0; j < 4; j++) acc[i][j] = 0.f;

    for (int c = 0; c < CIc; c++) {
        const float* qsrc = qb + (long)c * TVc;
        const float* ksrc = kb + (long)c * TVc;
        for (int li = tid; li < 64 * VV; li += 256) {
            int ttl = li / VV, v = li % VV;
            float qv = 0.f, kv = 0.f;
            if (t0 + ttl < TT) qv = qsrc[t0 * VV + li];
            if (q0 + ttl < TT) kv = ksrc[q0 * VV + li];
            Qs[v][ttl] = qv; Ks[v][ttl] = kv;
        }
        __syncthreads();
#pragma unroll
        for (int v = 0; v < VV; v++) {
            float a[4], bb[4];
#pragma unroll
            for (int i = 0; i < 4; i++) a[i] = Qs[v][ty * 4 + i];
#pragma unroll
            for (int j = 0; j < 4; j++) bb[j] = Ks[v][tx * 4 + j];
#pragma unroll
            for (int i = 0; i < 4; i++)
#pragma unroll
                for (int j = 0; j < 4; j++) acc[i][j] += a[i] * bb[j];
        }
        __syncthreads();
    }
    float al = alphat[s];
#pragma unroll
    for (int i = 0; i < 4; i++)
#pragma unroll
        for (int j = 0; j < 4; j++) {
            int t = t0 + ty * 4 + i, q = q0 + tx * 4 + j;
            if (t < TT && q < TT) {
                float val = tanhf(acc[i][j] * (1.f / (CIc * VV))) * al
                          + att0t[((long)s * TT + t) * TT + q];
                g_attt[(((long)(n * SS + s)) * TT + t) * TT + q] = val;
            }
        }
}

// ---------------- transpose to v-major: out[n][v][c][t] = in[n][c][t][v] ----------------
__global__ __launch_bounds__(256) void tr_vmajor_kernel(
    const float* __restrict__ in, float* __restrict__ out)
{
    __shared__ float sh[VV][33];
    int n = blockIdx.z, c = blockIdx.y, t0 = blockIdx.x * 32;
    int nmax = min(32, TT - t0);
    const float* src = in + ((long)(n * CC + c) * TT + t0) * VV;
    for (int li = threadIdx.x; li < nmax * VV; li += 256) {
        int t = li / VV, v = li % VV;
        sh[v][t] = src[li];
    }
    __syncthreads();
    for (int li = threadIdx.x; li < VV * 32; li += 256) {
        int v = li >> 5, t = li & 31;
        if (t < nmax)
            out[((long)(n * VV + v) * CC + c) * TT + t0 + t] = sh[v][t];
    }
}

// ---------------- final store: out[n][c][q][v] = inT[n][v][c][q] ----------------
__global__ __launch_bounds__(256) void store_out_kernel(
    const float* __restrict__ inT, float* __restrict__ out)
{
    __shared__ float sh[VV][33];
    int n = blockIdx.z, c = blockIdx.y, q0 = blockIdx.x * 32;
    int nmax = min(32, TT - q0);
    for (int li = threadIdx.x; li < VV * 32; li += 256) {
        int v = li >> 5, q = li & 31;
        if (q < nmax)
            sh[v][q] = inT[((long)(n * VV + v) * CC + c) * TT + q0 + q];
    }
    __syncthreads();
    float* dst = out + ((long)(n * CC + c) * TT + q0) * VV;
    for (int li = threadIdx.x; li < nmax * VV; li += 256) {
        int q = li / VV, v = li % VV;
        dst[li] = sh[v][q];
    }
}

// ---------------- host orchestration ----------------
static void run_stream(const float* xin, float* outp,
    const float* pe_s, const float* pe_t,
    const float* insB, const float* alphas, const float* att0s,
    const float* outsB, const float* outsG, const float* outsBe,
    const float* ffsB, const float* ffsG, const float* ffsBe,
    const float* intB, const float* alphat, const float* att0t,
    const float* outtB, const float* outtG, const float* outtBe,
    const float* fftB, const float* fftG, const float* fftBe,
    float* py, float* pqk, float* pz, float* ph, float* ps, float* psT, float* psTk,
    float* phT, float* poT,
    const float* wtIns, const float* wtOuts, const float* wtFfs,
    const float* wtInt, const float* wtOutt, const float* wtFft)
{
    const int addBlocks = (NN * CTVc / 4 + 255) / 256;
    const int PT = 157; // ceil(10000/64)

    // ===== spatial =====
    add_pe_kernel<<<addBlocks, 256>>>((const float4*)xin, (const float4*)pe_s, (float4*)py);
    gemm_tc<0><<<dim3(PT, 3, NN), 256>>>(wtIns, py, pqk, nullptr, insB, nullptr, nullptr,
                                         QKCc, CC, TVc, (long)CTVc, (long)QKCc * TVc);
    atts_kernel<<<NN * SS * VV, 256>>>(alphas, att0s);
    zspat_kernel<<<dim3((CC * TT + 255) / 256, NN), 256>>>(xin);
    gemm_tc<1><<<dim3(PT, 2, NN), 256>>>(wtOuts, pz, ph, xin, outsB, outsG, outsBe,
                                         CC, SCc, TVc, (long)SCc * TVc, (long)CTVc);
    gemm_tc<1><<<dim3(PT, 2, NN), 256>>>(wtFfs, ph, ps, xin, ffsB, ffsG, ffsBe,
                                         CC, CC, TVc, (long)CTVc, (long)CTVc);

    // ===== temporal =====
    add_pe_kernel<<<addBlocks, 256>>>((const float4*)ps, (const float4*)pe_t, (float4*)py);
    gemm_tc<0><<<dim3(PT, 3, NN), 256>>>(wtInt, py, pqk, nullptr, intB, nullptr, nullptr,
                                         QKCc, CC, TVc, (long)CTVc, (long)QKCc * TVc);
    attt_kernel<<<dim3(7, 7, NN * SS), 256>>>(alphat, att0t);
    tr_vmajor_kernel<<<dim3(13, CC, NN), 256>>>(ps, psT);
    transpose_b<<<dim3(13, 8, NN * VV), 256>>>(psT, psTk, CC, TT, (long)CC * TT, (long)CC * TT);
    ztemp_tc<<<dim3(7, 2, NN * SS * VV), 256>>>();
    gemm_tc<1><<<dim3(7, 2, NN * VV), 256>>>(wtOutt, pz, phT, psT, outtB, outtG, outtBe,
                                             CC, SCc, TT, (long)SCc * TT, (long)CC * TT);
    gemm_tc<1><<<dim3(7, 2, NN * VV), 256>>>(wtFft, phT, poT, psT, fftB, fftG, fftBe,
                                             CC, CC, TT, (long)CC * TT, (long)CC * TT);
    store_out_kernel<<<dim3(13, CC, NN), 256>>>(poT, outp);
}

extern "C" void kernel_launch(void* const* d_in, const int* in_sizes, int n_in,
                              void* d_out, int out_size)
{
    const float* x      = (const float*)d_in[0];
    const float* x1     = (const float*)d_in[1];
    const float* pe_s   = (const float*)d_in[2];
    const float* pe_t   = (const float*)d_in[3];
    const float* insW   = (const float*)d_in[4];
    const float* insB   = (const float*)d_in[5];
    const float* alphas = (const float*)d_in[6];
    const float* att0s  = (const float*)d_in[7];
    const float* outsW  = (const float*)d_in[8];
    const float* outsB  = (const float*)d_in[9];
    const float* outsG  = (const float*)d_in[10];
    const float* outsBe = (const float*)d_in[11];
    const float* ffsW   = (const float*)d_in[12];
    const float* ffsB   = (const float*)d_in[13];
    const float* ffsG   = (const float*)d_in[14];
    const float* ffsBe  = (const float*)d_in[15];
    const float* intW   = (const float*)d_in[16];
    const float* intB   = (const float*)d_in[17];
    const float* alphat = (const float*)d_in[18];
    const float* att0t  = (const float*)d_in[19];
    const float* outtW  = (const float*)d_in[20];
    const float* outtB  = (const float*)d_in[21];
    const float* outtG  = (const float*)d_in[22];
    const float* outtBe = (const float*)d_in[23];
    const float* fftW   = (const float*)d_in[24];
    const float* fftB   = (const float*)d_in[25];
    const float* fftG   = (const float*)d_in[26];
    const float* fftBe  = (const float*)d_in[27];

    float *py, *pqk, *pz, *ph, *ps, *psT, *psTk, *phT, *poT, *pwt;
    cudaGetSymbolAddress((void**)&py,   g_y);
    cudaGetSymbolAddress((void**)&pqk,  g_qk);
    cudaGetSymbolAddress((void**)&pz,   g_z);
    cudaGetSymbolAddress((void**)&ph,   g_h);
    cudaGetSymbolAddress((void**)&ps,   g_s);
    cudaGetSymbolAddress((void**)&psT,  g_sT);
    cudaGetSymbolAddress((void**)&psTk, g_sTk);
    cudaGetSymbolAddress((void**)&phT,  g_hT);
    cudaGetSymbolAddress((void**)&poT,  g_oT);
    cudaGetSymbolAddress((void**)&pwt,  g_wt);

    float* wtIns  = pwt + 0L * 768 * 256;
    float* wtOuts = pwt + 1L * 768 * 256;
    float* wtFfs  = pwt + 2L * 768 * 256;
    float* wtInt  = pwt + 3L * 768 * 256;
    float* wtOutt = pwt + 4L * 768 * 256;
    float* wtFft  = pwt + 5L * 768 * 256;

    // weight transposes to k-major (tiny)
    transpose_b<<<dim3(8, 12, 1), 256>>>(insW,  wtIns,  QKCc, CC, 0, 0);
    transpose_b<<<dim3(24, 8, 1), 256>>>(outsW, wtOuts, CC, SCc, 0, 0);
    transpose_b<<<dim3(8, 8, 1),  256>>>(ffsW,  wtFfs,  CC, CC, 0, 0);
    transpose_b<<<dim3(8, 12, 1), 256>>>(intW,  wtInt,  QKCc, CC, 0, 0);
    transpose_b<<<dim3(24, 8, 1), 256>>>(outtW, wtOutt, CC, SCc, 0, 0);
    transpose_b<<<dim3(8, 8, 1),  256>>>(fftW,  wtFft,  CC, CC, 0, 0);

    float* out = (float*)d_out;

    run_stream(x, out,
               pe_s, pe_t, insB, alphas, att0s, outsB, outsG, outsBe,
               ffsB, ffsG, ffsBe, intB, alphat, att0t,
               outtB, outtG, outtBe, fftB, fftG, fftBe,
               py, pqk, pz, ph, ps, psT, psTk, phT, poT,
               wtIns, wtOuts, wtFfs, wtInt, wtOutt, wtFft);

    run_stream(x1, out + (long)NN * CTVc,
               pe_s, pe_t, insB, alphas, att0s, outsB, outsG, outsBe,
               ffsB, ffsG, ffsBe, intB, alphat, att0t,
               outtB, outtG, outtBe, fftB, fftG, fftBe,
               py, pqk, pz, ph, ps, psT, psTk, phT, poT,
               wtIns, wtOuts, wtFfs, wtInt, wtOutt, wtFft);
}

// round 5
// speedup vs baseline: 2.1704x; 1.1236x over previous
#include <cuda_runtime.h>
#include <math.h>
#include <stdint.h>

// Problem constants
#define NB 8            // merged batch (2 streams x 4)
#define CC 256
#define TT 400
#define VV 25
#define SS 3
#define CIc 64
#define TVc (TT*VV)     // 10000
#define CTVc (CC*TVc)   // 2,560,000
#define QKCc (2*SS*CIc) // 384
#define SCc (SS*CC)     // 768

#define BK 16
#define BMp 136   // 128+8: row stride ≡ 8 (mod 32) -> conflict-free frag loads
#define BNp 72    // 64+8

// ---------------- scratch (static device globals; no allocation) ----------------
__device__ __align__(16) float g_x  [NB*CTVc];            // merged inputs (x | x1)
__device__ __align__(16) float g_qk [(long)NB*QKCc*TVc];
__device__ __align__(16) float g_atts[NB*SS*VV*VV];
__device__ __align__(16) float g_attt[(long)NB*SS*TT*TT];
__device__ __align__(16) float g_z  [(long)NB*SCc*TVc];
__device__ __align__(16) float g_h  [NB*CTVc];
__device__ __align__(16) float g_s  [NB*CTVc];
__device__ __align__(16) float g_sT [NB*CTVc];            // [n][v][c][t]
__device__ __align__(16) float g_sTk[NB*CTVc];            // [n][v][t][c]
__device__ __align__(16) float g_hT [NB*CTVc];
__device__ __align__(16) float g_oT [NB*CTVc];
__device__ __align__(16) float g_wt [6][768*256];         // k-major weights
__device__ __align__(16) float g_peqk[2][(long)QKCc*TVc]; // W*pe+b (spatial, temporal)

// ---------------- helpers ----------------
__device__ __forceinline__ uint32_t f2t(float x) {
    uint32_t u; asm("cvt.rna.tf32.f32 %0, %1;" : "=r"(u) : "f"(x));
    return u;
}
__device__ __forceinline__ void mma8(float* c, const uint32_t* a, const uint32_t* b) {
    asm volatile(
      "mma.sync.aligned.m16n8k8.row.col.f32.tf32.tf32.f32 "
      "{%0,%1,%2,%3}, {%4,%5,%6,%7}, {%8,%9}, {%0,%1,%2,%3};\n"
      : "+f"(c[0]), "+f"(c[1]), "+f"(c[2]), "+f"(c[3])
      : "r"(a[0]), "r"(a[1]), "r"(a[2]), "r"(a[3]), "r"(b[0]), "r"(b[1]));
}
__device__ __forceinline__ void cp16(uint32_t dst, const void* src, int szsrc) {
    asm volatile("cp.async.ca.shared.global [%0], [%1], 16, %2;\n"
                 :: "r"(dst), "l"(src), "r"(szsrc));
}
#define CP_COMMIT() asm volatile("cp.async.commit_group;\n" ::: "memory")
template<int N> __device__ __forceinline__ void cp_wait() {
    asm volatile("cp.async.wait_group %0;\n" :: "n"(N) : "memory");
}

// ---------------- tf32 tensor-core GEMM, cp.async 3-stage pipeline ----------------
// C[M,P] = At^T (At is K x M, k-major) * B (K x P row-major)
// EPI 0: C=acc+bias  1: C=lrelu(res+(acc+bias)*gam+bet)  2: C=acc  3: C=acc+res2d[m*P+p]
template<int EPI>
__device__ __forceinline__ void gemm_tc_body(
    const float* __restrict__ At, const float* __restrict__ B,
    float* __restrict__ C, const float* __restrict__ res,
    const float* __restrict__ bias, const float* __restrict__ gam, const float* __restrict__ bet,
    int M, int K, int P)
{
    __shared__ float As[3][BK][BMp];
    __shared__ float Bs[3][BK][BNp];
    const int m0 = blockIdx.y * 128;
    const int p0 = blockIdx.x * 64;
    const int tid = threadIdx.x;
    const int lane = tid & 31, warp = tid >> 5;
    const int g = lane >> 2, q4 = lane & 3;
    const int mbase = (warp >> 1) * 32;
    const int nbase = (warp & 1) * 32;

    float c[2][4][4];
#pragma unroll
    for (int mt = 0; mt < 2; mt++)
#pragma unroll
        for (int nt = 0; nt < 4; nt++)
#pragma unroll
            for (int k = 0; k < 4; k++) c[mt][nt][k] = 0.f;

    const int akk = tid >> 5, am = (tid & 31) * 4;
    const int bkk = tid >> 4, bp = (tid & 15) * 4;
    const float* aptr = At + (long)akk * M + m0 + am;
    const float* bptr = B + (long)bkk * P + p0 + bp;
    const int bsz = (p0 + bp < P) ? 16 : 0;

    const int niter = K / BK;

    auto issue = [&](int it) {
        int s = it % 3;
        long koff = (long)it * BK;
        cp16((uint32_t)__cvta_generic_to_shared(&As[s][akk][am]),     aptr + koff * M, 16);
        cp16((uint32_t)__cvta_generic_to_shared(&As[s][akk + 8][am]), aptr + (koff + 8) * M, 16);
        const float* bsrc = bsz ? (bptr + koff * P) : B;
        cp16((uint32_t)__cvta_generic_to_shared(&Bs[s][bkk][bp]), bsrc, bsz);
    };

    issue(0); CP_COMMIT();
    issue(1); CP_COMMIT();

    for (int it = 0; it < niter; it++) {
        cp_wait<1>();
        __syncthreads();
        if (it + 2 < niter) issue(it + 2);
        CP_COMMIT();
        const int s = it % 3;
#pragma unroll
        for (int k8 = 0; k8 < BK; k8 += 8) {
            uint32_t a[2][4], b[4][2];
#pragma unroll
            for (int mt = 0; mt < 2; mt++) {
                int mr = mbase + mt * 16 + g;
                a[mt][0] = f2t(As[s][k8 + q4    ][mr    ]);
                a[mt][1] = f2t(As[s][k8 + q4    ][mr + 8]);
                a[mt][2] = f2t(As[s][k8 + q4 + 4][mr    ]);
                a[mt][3] = f2t(As[s][k8 + q4 + 4][mr + 8]);
            }
#pragma unroll
            for (int nt = 0; nt < 4; nt++) {
                int nc = nbase + nt * 8 + g;
                b[nt][0] = f2t(Bs[s][k8 + q4    ][nc]);
                b[nt][1] = f2t(Bs[s][k8 + q4 + 4][nc]);
            }
#pragma unroll
            for (int mt = 0; mt < 2; mt++)
#pragma unroll
                for (int nt = 0; nt < 4; nt++)
                    mma8(c[mt][nt], a[mt], b[nt]);
        }
    }

    // epilogue
#pragma unroll
    for (int mt = 0; mt < 2; mt++) {
#pragma unroll
        for (int half = 0; half < 2; half++) {
            int r = m0 + mbase + mt * 16 + g + half * 8;
            float bi = 0.f, gm = 0.f, bt = 0.f;
            if (EPI == 0) bi = bias[r];
            if (EPI == 1) { bi = bias[r]; gm = gam[r]; bt = bet[r]; }
#pragma unroll
            for (int nt = 0; nt < 4; nt++) {
                int pc = p0 + nbase + nt * 8 + q4 * 2;
                if (pc < P) {  // P even -> pc+1 < P
                    long off = (long)r * P + pc;
                    float v0 = c[mt][nt][half * 2 + 0];
                    float v1 = c[mt][nt][half * 2 + 1];
                    if (EPI == 0) { v0 += bi; v1 += bi; }
                    if (EPI == 1) {
                        v0 = (v0 + bi) * gm + bt + res[off];
                        v1 = (v1 + bi) * gm + bt + res[off + 1];
                        v0 = (v0 >= 0.f) ? v0 : 0.1f * v0;
                        v1 = (v1 >= 0.f) ? v1 : 0.1f * v1;
                    }
                    if (EPI == 3) { v0 += res[off]; v1 += res[off + 1]; }
                    C[off] = v0; C[off + 1] = v1;
                }
            }
        }
    }
}

template<int EPI>
__global__ __launch_bounds__(256, 2) void gemm_tc(
    const float* __restrict__ At, const float* __restrict__ B, float* __restrict__ C,
    const float* __restrict__ res,
    const float* __restrict__ bias, const float* __restrict__ gam, const float* __restrict__ bet,
    int M, int K, int P, long sB, long sC, long sRes)
{
    long z = blockIdx.z;
    gemm_tc_body<EPI>(At, B + z * sB, C + z * sC,
                      res ? res + z * sRes : res, bias, gam, bet, M, K, P);
}

// temporal apply: z2T[(n,v)][s*C+c][q] = sum_t sTk[(n,v)][t][c] * attt[(n,s)][t][q]
__global__ __launch_bounds__(256, 2) void ztemp_tc()
{
    int z = blockIdx.z;
    int v = z % VV, s = (z / VV) % SS, n = z / (VV * SS);
    const float* At = g_sTk + (long)(n * VV + v) * TT * CC;   // 400 x 256 k-major
    const float* B  = g_attt + (long)(n * SS + s) * TT * TT;  // 400 x 400
    float* C = g_z + ((long)(n * VV + v) * SCc + s * CC) * TT;
    gemm_tc_body<2>(At, B, C, nullptr, nullptr, nullptr, nullptr, CC, TT, TT);
}

// ---------------- temporal attention via tf32 mma ----------------
// att[n,s,t,q] = tanh( sum_{c,v} q[c,t,v]k[c,q,v] / (CI*V) )*alpha + att0t
__global__ __launch_bounds__(256) void attt_tc(
    const float* __restrict__ alphat, const float* __restrict__ att0t)
{
    int ns = blockIdx.z; int n = ns / SS, s = ns % SS;
    int t0 = blockIdx.y * 64, q0 = blockIdx.x * 64;
    const float* qb = g_qk + ((long)n * QKCc + s * CIc) * TVc;
    const float* kb = g_qk + ((long)n * QKCc + (SS + s) * CIc) * TVc;
    __shared__ float Qs[32][72], Ks[32][72];
    int tid = threadIdx.x, lane = tid & 31, warp = tid >> 5;
    int g = lane >> 2, q4 = lane & 3;
    int mbase = (warp >> 2) * 32;   // 2 warp-rows of 32
    int nbase = (warp & 3) * 16;    // 4 warp-cols of 16

    // zero pad rows 25..31 once
    for (int i = tid; i < 7 * 72; i += 256) {
        int r = 25 + i / 72, col = i % 72;
        Qs[r][col] = 0.f; Ks[r][col] = 0.f;
    }

    float cc[2][2][4];
#pragma unroll
    for (int mt = 0; mt < 2; mt++)
#pragma unroll
        for (int nt = 0; nt < 2; nt++)
#pragma unroll
            for (int k = 0; k < 4; k++) cc[mt][nt][k] = 0.f;

    __syncthreads();

    for (int ch = 0; ch < CIc; ch++) {
        const float* qsrc = qb + (long)ch * TVc + t0 * VV;
        const float* ksrc = kb + (long)ch * TVc + q0 * VV;
        for (int li = tid; li < 64 * VV; li += 256) {
            int tt = li / VV, v = li % VV;
            float qv = (t0 + tt < TT) ? qsrc[li] : 0.f;
            float kv = (q0 + tt < TT) ? ksrc[li] : 0.f;
            Qs[v][tt] = qv; Ks[v][tt] = kv;
        }
        __syncthreads();
#pragma unroll
        for (int k8 = 0; k8 < 32; k8 += 8) {
            uint32_t a[2][4], b[2][2];
#pragma unroll
            for (int mt = 0; mt < 2; mt++) {
                int mr = mbase + mt * 16 + g;
                a[mt][0] = f2t(Qs[k8 + q4    ][mr    ]);
                a[mt][1] = f2t(Qs[k8 + q4    ][mr + 8]);
                a[mt][2] = f2t(Qs[k8 + q4 + 4][mr    ]);
                a[mt][3] = f2t(Qs[k8 + q4 + 4][mr + 8]);
            }
#pragma unroll
            for (int nt = 0; nt < 2; nt++) {
                int nc = nbase + nt * 8 + g;
                b[nt][0] = f2t(Ks[k8 + q4    ][nc]);
                b[nt][1] = f2t(Ks[k8 + q4 + 4][nc]);
            }
#pragma unroll
            for (int mt = 0; mt < 2; mt++)
#pragma unroll
                for (int nt = 0; nt < 2; nt++)
                    mma8(cc[mt][nt], a[mt], b[nt]);
        }
        __syncthreads();
    }

    float al = alphat[s];
#pragma unroll
    for (int mt = 0; mt < 2; mt++) {
#pragma unroll
        for (int half = 0; half < 2; half++) {
            int t = t0 + mbase + mt * 16 + g + half * 8;
#pragma unroll
            for (int nt = 0; nt < 2; nt++) {
                int q = q0 + nbase + nt * 8 + q4 * 2;
                if (t < TT && q < TT) {
                    long ob = (((long)(n * SS + s)) * TT + t) * TT + q;
                    long ab = ((long)s * TT + t) * TT + q;
                    float v0 = tanhf(cc[mt][nt][half * 2 + 0] * (1.f / (CIc * VV))) * al + att0t[ab];
                    float v1 = tanhf(cc[mt][nt][half * 2 + 1] * (1.f / (CIc * VV))) * al + att0t[ab + 1];
                    g_attt[ob] = v0; g_attt[ob + 1] = v1;
                }
            }
        }
    }
}

// ---------------- batched 2D transpose: out[z][k][m] = in[z][m][k] ----------------
__global__ __launch_bounds__(256) void transpose_b(
    const float* __restrict__ in, float* __restrict__ out,
    int M, int K, long sin, long sout)
{
    __shared__ float sh[32][33];
    const float* ip = in + (long)blockIdx.z * sin;
    float* op = out + (long)blockIdx.z * sout;
    int k0 = blockIdx.x * 32, m0 = blockIdx.y * 32;
    int tx = threadIdx.x & 31, ty = threadIdx.x >> 5;
    for (int i = ty; i < 32; i += 8) {
        int m = m0 + i, k = k0 + tx;
        if (m < M && k < K) sh[i][tx] = ip[(long)m * K + k];
    }
    __syncthreads();
    for (int i = ty; i < 32; i += 8) {
        int k = k0 + i, m = m0 + tx;
        if (k < K && m < M) op[(long)k * M + m] = sh[tx][i];
    }
}

// ---------------- spatial attention ----------------
__global__ __launch_bounds__(256) void atts_kernel(
    const float* __restrict__ alphas, const float* __restrict__ att0)
{
    int u = blockIdx.x % VV;
    int s = (blockIdx.x / VV) % SS;
    int n = blockIdx.x / (VV * SS);
    const float* qb = g_qk + ((long)n * QKCc + s * CIc) * TVc;
    const float* kb = g_qk + ((long)n * QKCc + (SS + s) * CIc) * TVc;
    float acc[VV];
#pragma unroll
    for (int v = 0; v < VV; v++) acc[v] = 0.f;
    int tid = threadIdx.x;
    for (int it = tid; it < CIc * TT; it += 256) {
        long base = (long)it * VV;
        float qv = qb[base + u];
#pragma unroll
        for (int v = 0; v < VV; v++) acc[v] += qv * kb[base + v];
    }
    __shared__ float sred[VV][256];
#pragma unroll
    for (int v = 0; v < VV; v++) sred[v][tid] = acc[v];
    __syncthreads();
    for (int st = 128; st > 0; st >>= 1) {
        if (tid < st) {
#pragma unroll
            for (int v = 0; v < VV; v++) sred[v][tid] += sred[v][tid + st];
        }
        __syncthreads();
    }
    if (tid < VV) {
        float val = tanhf(sred[tid][0] * (1.f / (CIc * TT))) * alphas[s]
                  + att0[(s * VV + u) * VV + tid];
        g_atts[((n * SS + s) * VV + u) * VV + tid] = val;
    }
}

// ---------------- spatial apply ----------------
__global__ __launch_bounds__(256) void zspat_kernel(const float* __restrict__ x)
{
    int n = blockIdx.y;
    __shared__ float att[SS * VV * VV];
    for (int i = threadIdx.x; i < SS * VV * VV; i += 256) att[i] = g_atts[n * SS * VV * VV + i];
    __syncthreads();
    int row = blockIdx.x * 256 + threadIdx.x;
    if (row >= CC * TT) return;
    int c = row / TT, t = row % TT;
    const float* xr = x + (long)n * CTVc + (long)row * VV;
    float xv[VV];
#pragma unroll
    for (int v = 0; v < VV; v++) xv[v] = xr[v];
#pragma unroll
    for (int s = 0; s < SS; s++) {
        float outv[VV];
#pragma unroll
        for (int w = 0; w < VV; w++) outv[w] = 0.f;
#pragma unroll
        for (int v = 0; v < VV; v++) {
            float xx = xv[v];
            const float* ar = &att[(s * VV + v) * VV];
#pragma unroll
            for (int w = 0; w < VV; w++) outv[w] += xx * ar[w];
        }
        float* zr = g_z + ((long)(n * SCc + s * CC + c)) * TVc + (long)t * VV;
#pragma unroll
        for (int w = 0; w < VV; w++) zr[w] = outv[w];
    }
}

// ---------------- transpose to v-major: out[n][v][c][t] = in[n][c][t][v] ----------------
__global__ __launch_bounds__(256) void tr_vmajor_kernel(
    const float* __restrict__ in, float* __restrict__ out)
{
    __shared__ float sh[VV][33];
    int n = blockIdx.z, c = blockIdx.y, t0 = blockIdx.x * 32;
    int nmax = min(32, TT - t0);
    const float* src = in + ((long)(n * CC + c) * TT + t0) * VV;
    for (int li = threadIdx.x; li < nmax * VV; li += 256) {
        int t = li / VV, v = li % VV;
        sh[v][t] = src[li];
    }
    __syncthreads();
    for (int li = threadIdx.x; li < VV * 32; li += 256) {
        int v = li >> 5, t = li & 31;
        if (t < nmax)
            out[((long)(n * VV + v) * CC + c) * TT + t0 + t] = sh[v][t];
    }
}

// ---------------- final store: out[n][c][q][v] = inT[n][v][c][q] ----------------
__global__ __launch_bounds__(256) void store_out_kernel(
    const float* __restrict__ inT, float* __restrict__ out)
{
    __shared__ float sh[VV][33];
    int n = blockIdx.z, c = blockIdx.y, q0 = blockIdx.x * 32;
    int nmax = min(32, TT - q0);
    for (int li = threadIdx.x; li < VV * 32; li += 256) {
        int v = li >> 5, q = li & 31;
        if (q < nmax)
            sh[v][q] = inT[((long)(n * VV + v) * CC + c) * TT + q0 + q];
    }
    __syncthreads();
    float* dst = out + ((long)(n * CC + c) * TT + q0) * VV;
    for (int li = threadIdx.x; li < nmax * VV; li += 256) {
        int q = li / VV, v = li % VV;
        dst[li] = sh[v][q];
    }
}

// ---------------- host orchestration ----------------
extern "C" void kernel_launch(void* const* d_in, const int* in_sizes, int n_in,
                              void* d_out, int out_size)
{
    const float* x      = (const float*)d_in[0];
    const float* x1     = (const float*)d_in[1];
    const float* pe_s   = (const float*)d_in[2];
    const float* pe_t   = (const float*)d_in[3];
    const float* insW   = (const float*)d_in[4];
    const float* insB   = (const float*)d_in[5];
    const float* alphas = (const float*)d_in[6];
    const float* att0s  = (const float*)d_in[7];
    const float* outsW  = (const float*)d_in[8];
    const float* outsB  = (const float*)d_in[9];
    const float* outsG  = (const float*)d_in[10];
    const float* outsBe = (const float*)d_in[11];
    const float* ffsW   = (const float*)d_in[12];
    const float* ffsB   = (const float*)d_in[13];
    const float* ffsG   = (const float*)d_in[14];
    const float* ffsBe  = (const float*)d_in[15];
    const float* intW   = (const float*)d_in[16];
    const float* intB   = (const float*)d_in[17];
    const float* alphat = (const float*)d_in[18];
    const float* att0t  = (const float*)d_in[19];
    const float* outtW  = (const float*)d_in[20];
    const float* outtB  = (const float*)d_in[21];
    const float* outtG  = (const float*)d_in[22];
    const float* outtBe = (const float*)d_in[23];
    const float* fftW   = (const float*)d_in[24];
    const float* fftB   = (const float*)d_in[25];
    const float* fftG   = (const float*)d_in[26];
    const float* fftBe  = (const float*)d_in[27];

    float *px, *pqk, *pz, *ph, *ps, *psT, *psTk, *phT, *poT, *pwt, *ppe;
    cudaGetSymbolAddress((void**)&px,   g_x);
    cudaGetSymbolAddress((void**)&pqk,  g_qk);
    cudaGetSymbolAddress((void**)&pz,   g_z);
    cudaGetSymbolAddress((void**)&ph,   g_h);
    cudaGetSymbolAddress((void**)&ps,   g_s);
    cudaGetSymbolAddress((void**)&psT,  g_sT);
    cudaGetSymbolAddress((void**)&psTk, g_sTk);
    cudaGetSymbolAddress((void**)&phT,  g_hT);
    cudaGetSymbolAddress((void**)&poT,  g_oT);
    cudaGetSymbolAddress((void**)&pwt,  g_wt);
    cudaGetSymbolAddress((void**)&ppe,  g_peqk);

    float* wtIns  = pwt + 0L * 768 * 256;
    float* wtOuts = pwt + 1L * 768 * 256;
    float* wtFfs  = pwt + 2L * 768 * 256;
    float* wtInt  = pwt + 3L * 768 * 256;
    float* wtOutt = pwt + 4L * 768 * 256;
    float* wtFft  = pwt + 5L * 768 * 256;
    float* peS = ppe;
    float* peT = ppe + (long)QKCc * TVc;

    const long halfBytes = (long)(NB / 2) * CTVc * sizeof(float);
    cudaMemcpyAsync(px, x, halfBytes, cudaMemcpyDeviceToDevice);
    cudaMemcpyAsync(px + (long)(NB / 2) * CTVc, x1, halfBytes, cudaMemcpyDeviceToDevice);

    // weight transposes to k-major
    transpose_b<<<dim3(8, 12, 1), 256>>>(insW,  wtIns,  QKCc, CC, 0, 0);
    transpose_b<<<dim3(24, 8, 1), 256>>>(outsW, wtOuts, CC, SCc, 0, 0);
    transpose_b<<<dim3(8, 8, 1),  256>>>(ffsW,  wtFfs,  CC, CC, 0, 0);
    transpose_b<<<dim3(8, 12, 1), 256>>>(intW,  wtInt,  QKCc, CC, 0, 0);
    transpose_b<<<dim3(24, 8, 1), 256>>>(outtW, wtOutt, CC, SCc, 0, 0);
    transpose_b<<<dim3(8, 8, 1),  256>>>(fftW,  wtFft,  CC, CC, 0, 0);

    const int PT = 157; // ceil(10000/64)

    // PEQK = W*pe + b (folds bias + positional encoding into one 2D map)
    gemm_tc<0><<<dim3(PT, 3, 1), 256>>>(wtIns, pe_s, peS, nullptr, insB, nullptr, nullptr,
                                        QKCc, CC, TVc, 0, 0, 0);
    gemm_tc<0><<<dim3(PT, 3, 1), 256>>>(wtInt, pe_t, peT, nullptr, intB, nullptr, nullptr,
                                        QKCc, CC, TVc, 0, 0, 0);

    // ===== spatial (batch 8) =====
    gemm_tc<3><<<dim3(PT, 3, NB), 256>>>(wtIns, px, pqk, peS, nullptr, nullptr, nullptr,
                                         QKCc, CC, TVc, (long)CTVc, (long)QKCc * TVc, 0);
    atts_kernel<<<NB * SS * VV, 256>>>(alphas, att0s);
    zspat_kernel<<<dim3((CC * TT + 255) / 256, NB), 256>>>(px);
    gemm_tc<1><<<dim3(PT, 2, NB), 256>>>(wtOuts, pz, ph, px, outsB, outsG, outsBe,
                                         CC, SCc, TVc, (long)SCc * TVc, (long)CTVc, (long)CTVc);
    gemm_tc<1><<<dim3(PT, 2, NB), 256>>>(wtFfs, ph, ps, px, ffsB, ffsG, ffsBe,
                                         CC, CC, TVc, (long)CTVc, (long)CTVc, (long)CTVc);

    // ===== temporal (batch 8) =====
    gemm_tc<3><<<dim3(PT, 3, NB), 256>>>(wtInt, ps, pqk, peT, nullptr, nullptr, nullptr,
                                         QKCc, CC, TVc, (long)CTVc, (long)QKCc * TVc, 0);
    attt_tc<<<dim3(7, 7, NB * SS), 256>>>(alphat, att0t);
    tr_vmajor_kernel<<<dim3(13, CC, NB), 256>>>(ps, psT);
    transpose_b<<<dim3(13, 8, NB * VV), 256>>>(psT, psTk, CC, TT, (long)CC * TT, (long)CC * TT);
    ztemp_tc<<<dim3(7, 2, NB * SS * VV), 256>>>();
    gemm_tc<1><<<dim3(7, 2, NB * VV), 256>>>(wtOutt, pz, phT, psT, outtB, outtG, outtBe,
                                             CC, SCc, TT, (long)SCc * TT, (long)CC * TT, (long)CC * TT);
    gemm_tc<1><<<dim3(7, 2, NB * VV), 256>>>(wtFft, phT, poT, psT, fftB, fftG, fftBe,
                                             CC, CC, TT, (long)CC * TT, (long)CC * TT, (long)CC * TT);
    store_out_kernel<<<dim3(13, CC, NB), 256>>>(poT, (float*)d_out);
}

// round 6
// speedup vs baseline: 2.5806x; 1.1890x over previous
#include <cuda_runtime.h>
#include <math.h>
#include <stdint.h>

// Problem constants
#define NB 8            // merged batch (2 streams x 4)
#define CC 256
#define TT 400
#define VV 25
#define SS 3
#define CIc 64
#define TVc (TT*VV)     // 10000
#define CTVc (CC*TVc)   // 2,560,000
#define QKCc (2*SS*CIc) // 384
#define SCc (SS*CC)     // 768

#define BK 16
#define BMp 136   // 128+8: row stride ≡ 8 (mod 32) -> conflict-free frag loads

// ---------------- scratch (static device globals; no allocation) ----------------
__device__ __align__(16) float g_x  [NB*CTVc];            // merged inputs, tf32-rounded
__device__ __align__(16) float g_pe [2][CTVc];            // rounded pe_s, pe_t
__device__ __align__(16) float g_qk [(long)NB*QKCc*TVc];
__device__ __align__(16) float g_atts[NB*SS*VV*VV];
__device__ __align__(16) float g_attt[(long)NB*SS*TT*TT];
__device__ __align__(16) float g_z  [(long)NB*SCc*TVc];
__device__ __align__(16) float g_h  [NB*CTVc];
__device__ __align__(16) float g_s  [NB*CTVc];
__device__ __align__(16) float g_sT [NB*CTVc];            // [n][v][c][t]
__device__ __align__(16) float g_sTk[NB*CTVc];            // [n][v][t][c]
__device__ __align__(16) float g_hT [NB*CTVc];
__device__ __align__(16) float g_oT [NB*CTVc];
__device__ __align__(16) float g_wt [6][768*256];         // k-major tf32-rounded weights
__device__ __align__(16) float g_peqk[2][(long)QKCc*TVc]; // W*pe+b

// ---------------- helpers ----------------
__device__ __forceinline__ float rnd(float x) {
    uint32_t u; asm("cvt.rna.tf32.f32 %0, %1;" : "=r"(u) : "f"(x));
    return __uint_as_float(u);
}
__device__ __forceinline__ void mma8(float* c, const uint32_t* a, const uint32_t* b) {
    asm volatile(
      "mma.sync.aligned.m16n8k8.row.col.f32.tf32.tf32.f32 "
      "{%0,%1,%2,%3}, {%4,%5,%6,%7}, {%8,%9}, {%0,%1,%2,%3};\n"
      : "+f"(c[0]), "+f"(c[1]), "+f"(c[2]), "+f"(c[3])
      : "r"(a[0]), "r"(a[1]), "r"(a[2]), "r"(a[3]), "r"(b[0]), "r"(b[1]));
}
__device__ __forceinline__ void cp16(uint32_t dst, const void* src, int szsrc) {
    asm volatile("cp.async.ca.shared.global [%0], [%1], 16, %2;\n"
                 :: "r"(dst), "l"(src), "r"(szsrc));
}
#define CP_COMMIT() asm volatile("cp.async.commit_group;\n" ::: "memory")
template<int N> __device__ __forceinline__ void cp_wait() {
    asm volatile("cp.async.wait_group %0;\n" :: "n"(N) : "memory");
}

// ---------------- tf32 GEMM, 128x128 tile, cp.async 3-stage ----------------
// C[M,P] = At^T (At is K x M, k-major, pre-rounded) * B (K x P row-major, pre-rounded)
// EPI 0: C=acc+bias  1: C=lrelu(res+(acc+bias)*gam+bet)  2: C=acc  3: C=acc+res2d[m*P+p]
// RND: round output to tf32 at store (for GEMM-consumed intermediates)
template<int EPI, int RND>
__device__ __forceinline__ void gemm_tc_body(
    const float* __restrict__ At, const float* __restrict__ B,
    float* __restrict__ C, const float* __restrict__ res,
    const float* __restrict__ bias, const float* __restrict__ gam, const float* __restrict__ bet,
    int M, int K, int P)
{
    __shared__ float As[3][BK][BMp];
    __shared__ float Bs[3][BK][BMp];
    const int m0 = blockIdx.y * 128;
    const int p0 = blockIdx.x * 128;
    const int tid = threadIdx.x;
    const int lane = tid & 31, warp = tid >> 5;
    const int g = lane >> 2, q4 = lane & 3;
    const int mbase = (warp >> 2) * 64;  // 2 warp rows
    const int nbase = (warp & 3) * 32;   // 4 warp cols

    float c[4][4][4];
#pragma unroll
    for (int mt = 0; mt < 4; mt++)
#pragma unroll
        for (int nt = 0; nt < 4; nt++)
#pragma unroll
            for (int k = 0; k < 4; k++) c[mt][nt][k] = 0.f;

    const int niter = K / BK;

    auto issue = [&](int it) {
        int s = it % 3;
        long koff = (long)it * BK;
#pragma unroll
        for (int i = 0; i < 2; i++) {
            int li = tid + 256 * i;
            int kk = li >> 5, col = (li & 31) * 4;
            cp16((uint32_t)__cvta_generic_to_shared(&As[s][kk][col]),
                 At + (koff + kk) * M + m0 + col, 16);
            int p = p0 + col;
            const float* bsrc = (p < P) ? (B + (koff + kk) * P + p) : B;
            cp16((uint32_t)__cvta_generic_to_shared(&Bs[s][kk][col]),
                 bsrc, (p < P) ? 16 : 0);
        }
    };

    issue(0); CP_COMMIT();
    issue(1); CP_COMMIT();

    for (int it = 0; it < niter; it++) {
        cp_wait<1>();
        __syncthreads();
        if (it + 2 < niter) issue(it + 2);
        CP_COMMIT();
        const int s = it % 3;
#pragma unroll
        for (int k8 = 0; k8 < BK; k8 += 8) {
            uint32_t a[4][4], b[4][2];
#pragma unroll
            for (int mt = 0; mt < 4; mt++) {
                int mr = mbase + mt * 16 + g;
                a[mt][0] = __float_as_uint(As[s][k8 + q4    ][mr    ]);
                a[mt][1] = __float_as_uint(As[s][k8 + q4    ][mr + 8]);
                a[mt][2] = __float_as_uint(As[s][k8 + q4 + 4][mr    ]);
                a[mt][3] = __float_as_uint(As[s][k8 + q4 + 4][mr + 8]);
            }
#pragma unroll
            for (int nt = 0; nt < 4; nt++) {
                int nc = nbase + nt * 8 + g;
                b[nt][0] = __float_as_uint(Bs[s][k8 + q4    ][nc]);
                b[nt][1] = __float_as_uint(Bs[s][k8 + q4 + 4][nc]);
            }
#pragma unroll
            for (int mt = 0; mt < 4; mt++)
#pragma unroll
                for (int nt = 0; nt < 4; nt++)
                    mma8(c[mt][nt], a[mt], b[nt]);
        }
    }

    // epilogue
#pragma unroll
    for (int mt = 0; mt < 4; mt++) {
#pragma unroll
        for (int half = 0; half < 2; half++) {
            int r = m0 + mbase + mt * 16 + g + half * 8;
            float bi = 0.f, gm = 0.f, bt = 0.f;
            if (EPI == 0) bi = bias[r];
            if (EPI == 1) { bi = bias[r]; gm = gam[r]; bt = bet[r]; }
#pragma unroll
            for (int nt = 0; nt < 4; nt++) {
                int pc = p0 + nbase + nt * 8 + q4 * 2;
                if (pc < P) {   // P even -> pc+1 < P
                    long off = (long)r * P + pc;
                    float v0 = c[mt][nt][half * 2 + 0];
                    float v1 = c[mt][nt][half * 2 + 1];
                    if (EPI == 0) { v0 += bi; v1 += bi; }
                    if (EPI == 1) {
                        v0 = (v0 + bi) * gm + bt + res[off];
                        v1 = (v1 + bi) * gm + bt + res[off + 1];
                        v0 = (v0 >= 0.f) ? v0 : 0.1f * v0;
                        v1 = (v1 >= 0.f) ? v1 : 0.1f * v1;
                    }
                    if (EPI == 3) { v0 += res[off]; v1 += res[off + 1]; }
                    if (RND) { v0 = rnd(v0); v1 = rnd(v1); }
                    C[off] = v0; C[off + 1] = v1;
                }
            }
        }
    }
}

template<int EPI, int RND>
__global__ __launch_bounds__(256, 2) void gemm_tc(
    const float* __restrict__ At, const float* __restrict__ B, float* __restrict__ C,
    const float* __restrict__ res,
    const float* __restrict__ bias, const float* __restrict__ gam, const float* __restrict__ bet,
    int M, int K, int P, long sB, long sC, long sRes)
{
    long z = blockIdx.z;
    gemm_tc_body<EPI, RND>(At, B + z * sB, C + z * sC,
                           res ? res + z * sRes : res, bias, gam, bet, M, K, P);
}

// temporal apply: z2T[(n,v)][s*C+c][q] = sum_t sTk[(n,v)][t][c] * attt[(n,s)][t][q]
__global__ __launch_bounds__(256, 2) void ztemp_tc()
{
    int z = blockIdx.z;
    int v = z % VV, s = (z / VV) % SS, n = z / (VV * SS);
    const float* At = g_sTk + (long)(n * VV + v) * TT * CC;   // 400 x 256 k-major
    const float* B  = g_attt + (long)(n * SS + s) * TT * TT;  // 400 x 400
    float* C = g_z + ((long)(n * VV + v) * SCc + s * CC) * TT;
    gemm_tc_body<2, 1>(At, B, C, nullptr, nullptr, nullptr, nullptr, CC, TT, TT);
}

// ---------------- temporal attention via tf32 mma (inputs pre-rounded) ----------------
__global__ __launch_bounds__(256) void attt_tc(
    const float* __restrict__ alphat, const float* __restrict__ att0t)
{
    int ns = blockIdx.z; int n = ns / SS, s = ns % SS;
    int t0 = blockIdx.y * 64, q0 = blockIdx.x * 64;
    const float* qb = g_qk + ((long)n * QKCc + s * CIc) * TVc;
    const float* kb = g_qk + ((long)n * QKCc + (SS + s) * CIc) * TVc;
    __shared__ float Qs[32][72], Ks[32][72];
    int tid = threadIdx.x, lane = tid & 31, warp = tid >> 5;
    int g = lane >> 2, q4 = lane & 3;
    int mbase = (warp >> 2) * 32;
    int nbase = (warp & 3) * 16;

    for (int i = tid; i < 7 * 72; i += 256) {
        int r = 25 + i / 72, col = i % 72;
        Qs[r][col] = 0.f; Ks[r][col] = 0.f;
    }

    float cc[2][2][4];
#pragma unroll
    for (int mt = 0; mt < 2; mt++)
#pragma unroll
        for (int nt = 0; nt < 2; nt++)
#pragma unroll
            for (int k = 0; k < 4; k++) cc[mt][nt][k] = 0.f;

    __syncthreads();

    for (int ch = 0; ch < CIc; ch++) {
        const float* qsrc = qb + (long)ch * TVc + t0 * VV;
        const float* ksrc = kb + (long)ch * TVc + q0 * VV;
        for (int li = tid; li < 64 * VV; li += 256) {
            int tt = li / VV, v = li % VV;
            float qv = (t0 + tt < TT) ? qsrc[li] : 0.f;
            float kv = (q0 + tt < TT) ? ksrc[li] : 0.f;
            Qs[v][tt] = qv; Ks[v][tt] = kv;
        }
        __syncthreads();
#pragma unroll
        for (int k8 = 0; k8 < 32; k8 += 8) {
            uint32_t a[2][4], b[2][2];
#pragma unroll
            for (int mt = 0; mt < 2; mt++) {
                int mr = mbase + mt * 16 + g;
                a[mt][0] = __float_as_uint(Qs[k8 + q4    ][mr    ]);
                a[mt][1] = __float_as_uint(Qs[k8 + q4    ][mr + 8]);
                a[mt][2] = __float_as_uint(Qs[k8 + q4 + 4][mr    ]);
                a[mt][3] = __float_as_uint(Qs[k8 + q4 + 4][mr + 8]);
            }
#pragma unroll
            for (int nt = 0; nt < 2; nt++) {
                int nc = nbase + nt * 8 + g;
                b[nt][0] = __float_as_uint(Ks[k8 + q4    ][nc]);
                b[nt][1] = __float_as_uint(Ks[k8 + q4 + 4][nc]);
            }
#pragma unroll
            for (int mt = 0; mt < 2; mt++)
#pragma unroll
                for (int nt = 0; nt < 2; nt++)
                    mma8(cc[mt][nt], a[mt], b[nt]);
        }
        __syncthreads();
    }

    float al = alphat[s];
#pragma unroll
    for (int mt = 0; mt < 2; mt++) {
#pragma unroll
        for (int half = 0; half < 2; half++) {
            int t = t0 + mbase + mt * 16 + g + half * 8;
#pragma unroll
            for (int nt = 0; nt < 2; nt++) {
                int q = q0 + nbase + nt * 8 + q4 * 2;
                if (t < TT && q < TT) {
                    long ob = (((long)(n * SS + s)) * TT + t) * TT + q;
                    long ab = ((long)s * TT + t) * TT + q;
                    float v0 = tanhf(cc[mt][nt][half * 2 + 0] * (1.f / (CIc * VV))) * al + att0t[ab];
                    float v1 = tanhf(cc[mt][nt][half * 2 + 1] * (1.f / (CIc * VV))) * al + att0t[ab + 1];
                    g_attt[ob] = rnd(v0); g_attt[ob + 1] = rnd(v1);   // feeds ztemp B
                }
            }
        }
    }
}

// ---------------- batched 2D transpose with tf32 rounding: out[z][k][m] = in[z][m][k] ----------------
__global__ __launch_bounds__(256) void transpose_b(
    const float* __restrict__ in, float* __restrict__ out,
    int M, int K, long sin, long sout)
{
    __shared__ float sh[32][33];
    const float* ip = in + (long)blockIdx.z * sin;
    float* op = out + (long)blockIdx.z * sout;
    int k0 = blockIdx.x * 32, m0 = blockIdx.y * 32;
    int tx = threadIdx.x & 31, ty = threadIdx.x >> 5;
    for (int i = ty; i < 32; i += 8) {
        int m = m0 + i, k = k0 + tx;
        if (m < M && k < K) sh[i][tx] = ip[(long)m * K + k];
    }
    __syncthreads();
    for (int i = ty; i < 32; i += 8) {
        int k = k0 + i, m = m0 + tx;
        if (k < K && m < M) op[(long)k * M + m] = rnd(sh[tx][i]);
    }
}

// ---------------- round-copy (merge inputs / pe) ----------------
__global__ __launch_bounds__(256) void round_copy(
    const float4* __restrict__ in, float4* __restrict__ out, int n4)
{
    int i = blockIdx.x * 256 + threadIdx.x;
    if (i >= n4) return;
    float4 a = in[i];
    a.x = rnd(a.x); a.y = rnd(a.y); a.z = rnd(a.z); a.w = rnd(a.w);
    out[i] = a;
}

// ---------------- spatial attention: 5 u's per block, full register accumulation ----------------
__global__ __launch_bounds__(256) void atts_kernel(
    const float* __restrict__ alphas, const float* __restrict__ att0)
{
    int ug = blockIdx.x;              // u group (5 groups of 5)
    int ns = blockIdx.y; int n = ns / SS, s = ns % SS;
    const float* qb = g_qk + ((long)n * QKCc + s * CIc) * TVc;
    const float* kb = g_qk + ((long)n * QKCc + (SS + s) * CIc) * TVc;
    int u0 = ug * 5;
    int tid = threadIdx.x, lane = tid & 31, warp = tid >> 5;

    float acc[5][VV];
#pragma unroll
    for (int j = 0; j < 5; j++)
#pragma unroll
        for (int v = 0; v < VV; v++) acc[j][v] = 0.f;

    for (int it = tid; it < CIc * TT; it += 256) {
        long base = (long)it * VV;
        float kv[VV];
#pragma unroll
        for (int v = 0; v < VV; v++) kv[v] = kb[base + v];
#pragma unroll
        for (int j = 0; j < 5; j++) {
            float qv = qb[base + u0 + j];
#pragma unroll
            for (int v = 0; v < VV; v++) acc[j][v] += qv * kv[v];
        }
    }
    // warp reduce
#pragma unroll
    for (int j = 0; j < 5; j++)
#pragma unroll
        for (int v = 0; v < VV; v++)
#pragma unroll
            for (int off = 16; off > 0; off >>= 1)
                acc[j][v] += __shfl_xor_sync(0xffffffffu, acc[j][v], off);
    __shared__ float sred[8][5][VV];
    if (lane == 0)
#pragma unroll
        for (int j = 0; j < 5; j++)
#pragma unroll
            for (int v = 0; v < VV; v++) sred[warp][j][v] = acc[j][v];
    __syncthreads();
    if (tid < 5 * VV) {
        int j = tid / VV, v = tid % VV;
        float sum = 0.f;
#pragma unroll
        for (int w = 0; w < 8; w++) sum += sred[w][j][v];
        int u = u0 + j;
        float val = tanhf(sum * (1.f / (CIc * TT))) * alphas[s]
                  + att0[(s * VV + u) * VV + v];
        g_atts[((n * SS + s) * VV + u) * VV + v] = val;
    }
}

// ---------------- spatial apply: 2 t's per thread, float2 I/O, rounded output ----------------
__global__ __launch_bounds__(256) void zspat_kernel(const float* __restrict__ x)
{
    int n = blockIdx.y;
    __shared__ float att[SS * VV * VV];
    for (int i = threadIdx.x; i < SS * VV * VV; i += 256) att[i] = g_atts[n * SS * VV * VV + i];
    __syncthreads();
    int rp = blockIdx.x * 256 + threadIdx.x;   // over CC * TT/2
    if (rp >= CC * (TT / 2)) return;
    int c = rp / (TT / 2), tp = rp % (TT / 2);
    const float2* xr = (const float2*)(x + (long)n * CTVc + (long)c * TVc + (long)tp * 2 * VV);
    float r[2 * VV];
#pragma unroll
    for (int i = 0; i < VV; i++) { float2 f = xr[i]; r[2 * i] = f.x; r[2 * i + 1] = f.y; }
#pragma unroll
    for (int s = 0; s < SS; s++) {
        float o[2 * VV];
#pragma unroll
        for (int w = 0; w < 2 * VV; w++) o[w] = 0.f;
#pragma unroll
        for (int v = 0; v < VV; v++) {
            float x0 = r[v], x1 = r[VV + v];
            const float* ar = &att[(s * VV + v) * VV];
#pragma unroll
            for (int w = 0; w < VV; w++) { o[w] += x0 * ar[w]; o[VV + w] += x1 * ar[w]; }
        }
        float2* zr = (float2*)(g_z + ((long)(n * SCc + s * CC + c)) * TVc + (long)tp * 2 * VV);
#pragma unroll
        for (int i = 0; i < VV; i++) {
            float2 f; f.x = rnd(o[2 * i]); f.y = rnd(o[2 * i + 1]);
            zr[i] = f;
        }
    }
}

// ---------------- transpose to v-major: out[n][v][c][t] = in[n][c][t][v] ----------------
__global__ __launch_bounds__(256) void tr_vmajor_kernel(
    const float* __restrict__ in, float* __restrict__ out)
{
    __shared__ float sh[VV][33];
    int n = blockIdx.z, c = blockIdx.y, t0 = blockIdx.x * 32;
    int nmax = min(32, TT - t0);
    const float* src = in + ((long)(n * CC + c) * TT + t0) * VV;
    for (int li = threadIdx.x; li < nmax * VV; li += 256) {
        int t = li / VV, v = li % VV;
        sh[v][t] = src[li];
    }
    __syncthreads();
    for (int li = threadIdx.x; li < VV * 32; li += 256) {
        int v = li >> 5, t = li & 31;
        if (t < nmax)
            out[((long)(n * VV + v) * CC + c) * TT + t0 + t] = sh[v][t];
    }
}

// ---------------- final store: out[n][c][q][v] = inT[n][v][c][q] ----------------
__global__ __launch_bounds__(256) void store_out_kernel(
    const float* __restrict__ inT, float* __restrict__ out)
{
    __shared__ float sh[VV][33];
    int n = blockIdx.z, c = blockIdx.y, q0 = blockIdx.x * 32;
    int nmax = min(32, TT - q0);
    for (int li = threadIdx.x; li < VV * 32; li += 256) {
        int v = li >> 5, q = li & 31;
        if (q < nmax)
            sh[v][q] = inT[((long)(n * VV + v) * CC + c) * TT + q0 + q];
    }
    __syncthreads();
    float* dst = out + ((long)(n * CC + c) * TT + q0) * VV;
    for (int li = threadIdx.x; li < nmax * VV; li += 256) {
        int q = li / VV, v = li % VV;
        dst[li] = sh[v][q];
    }
}

// ---------------- host orchestration ----------------
extern "C" void kernel_launch(void* const* d_in, const int* in_sizes, int n_in,
                              void* d_out, int out_size)
{
    const float* x      = (const float*)d_in[0];
    const float* x1     = (const float*)d_in[1];
    const float* pe_s   = (const float*)d_in[2];
    const float* pe_t   = (const float*)d_in[3];
    const float* insW   = (const float*)d_in[4];
    const float* insB   = (const float*)d_in[5];
    const float* alphas = (const float*)d_in[6];
    const float* att0s  = (const float*)d_in[7];
    const float* outsW  = (const float*)d_in[8];
    const float* outsB  = (const float*)d_in[9];
    const float* outsG  = (const float*)d_in[10];
    const float* outsBe = (const float*)d_in[11];
    const float* ffsW   = (const float*)d_in[12];
    const float* ffsB   = (const float*)d_in[13];
    const float* ffsG   = (const float*)d_in[14];
    const float* ffsBe  = (const float*)d_in[15];
    const float* intW   = (const float*)d_in[16];
    const float* intB   = (const float*)d_in[17];
    const float* alphat = (const float*)d_in[18];
    const float* att0t  = (const float*)d_in[19];
    const float* outtW  = (const float*)d_in[20];
    const float* outtB  = (const float*)d_in[21];
    const float* outtG  = (const float*)d_in[22];
    const float* outtBe = (const float*)d_in[23];
    const float* fftW   = (const float*)d_in[24];
    const float* fftB   = (const float*)d_in[25];
    const float* fftG   = (const float*)d_in[26];
    const float* fftBe  = (const float*)d_in[27];

    float *px, *pqk, *pz, *ph, *ps, *psT, *psTk, *phT, *poT, *pwt, *ppeqk, *ppe;
    cudaGetSymbolAddress((void**)&px,    g_x);
    cudaGetSymbolAddress((void**)&pqk,   g_qk);
    cudaGetSymbolAddress((void**)&pz,    g_z);
    cudaGetSymbolAddress((void**)&ph,    g_h);
    cudaGetSymbolAddress((void**)&ps,    g_s);
    cudaGetSymbolAddress((void**)&psT,   g_sT);
    cudaGetSymbolAddress((void**)&psTk,  g_sTk);
    cudaGetSymbolAddress((void**)&phT,   g_hT);
    cudaGetSymbolAddress((void**)&poT,   g_oT);
    cudaGetSymbolAddress((void**)&pwt,   g_wt);
    cudaGetSymbolAddress((void**)&ppeqk, g_peqk);
    cudaGetSymbolAddress((void**)&ppe,   g_pe);

    float* wtIns  = pwt + 0L * 768 * 256;
    float* wtOuts = pwt + 1L * 768 * 256;
    float* wtFfs  = pwt + 2L * 768 * 256;
    float* wtInt  = pwt + 3L * 768 * 256;
    float* wtOutt = pwt + 4L * 768 * 256;
    float* wtFft  = pwt + 5L * 768 * 256;
    float* peS = ppeqk;
    float* peT = ppeqk + (long)QKCc * TVc;
    float* rpeS = ppe;
    float* rpeT = ppe + (long)CTVc;

    const int half4 = (NB / 2) * CTVc / 4;
    round_copy<<<(half4 + 255) / 256, 256>>>((const float4*)x,  (float4*)px, half4);
    round_copy<<<(half4 + 255) / 256, 256>>>((const float4*)x1, (float4*)(px + (long)(NB / 2) * CTVc), half4);
    round_copy<<<(CTVc / 4 + 255) / 256, 256>>>((const float4*)pe_s, (float4*)rpeS, CTVc / 4);
    round_copy<<<(CTVc / 4 + 255) / 256, 256>>>((const float4*)pe_t, (float4*)rpeT, CTVc / 4);

    // weight transposes to k-major (rounded)
    transpose_b<<<dim3(8, 12, 1), 256>>>(insW,  wtIns,  QKCc, CC, 0, 0);
    transpose_b<<<dim3(24, 8, 1), 256>>>(outsW, wtOuts, CC, SCc, 0, 0);
    transpose_b<<<dim3(8, 8, 1),  256>>>(ffsW,  wtFfs,  CC, CC, 0, 0);
    transpose_b<<<dim3(8, 12, 1), 256>>>(intW,  wtInt,  QKCc, CC, 0, 0);
    transpose_b<<<dim3(24, 8, 1), 256>>>(outtW, wtOutt, CC, SCc, 0, 0);
    transpose_b<<<dim3(8, 8, 1),  256>>>(fftW,  wtFft,  CC, CC, 0, 0);

    const int PT = 79;  // ceil(10000/128)
    const int PQ = 4;   // ceil(400/128)

    // PEQK = W*pe + b
    gemm_tc<0, 1><<<dim3(PT, 3, 1), 256>>>(wtIns, rpeS, peS, nullptr, insB, nullptr, nullptr,
                                           QKCc, CC, TVc, 0, 0, 0);
    gemm_tc<0, 1><<<dim3(PT, 3, 1), 256>>>(wtInt, rpeT, peT, nullptr, intB, nullptr, nullptr,
                                           QKCc, CC, TVc, 0, 0, 0);

    // ===== spatial (batch 8) =====
    gemm_tc<3, 1><<<dim3(PT, 3, NB), 256>>>(wtIns, px, pqk, peS, nullptr, nullptr, nullptr,
                                            QKCc, CC, TVc, (long)CTVc, (long)QKCc * TVc, 0);
    atts_kernel<<<dim3(5, NB * SS), 256>>>(alphas, att0s);
    zspat_kernel<<<dim3(CC * (TT / 2) / 256, NB), 256>>>(px);
    gemm_tc<1, 1><<<dim3(PT, 2, NB), 256>>>(wtOuts, pz, ph, px, outsB, outsG, outsBe,
                                            CC, SCc, TVc, (long)SCc * TVc, (long)CTVc, (long)CTVc);
    gemm_tc<1, 1><<<dim3(PT, 2, NB), 256>>>(wtFfs, ph, ps, px, ffsB, ffsG, ffsBe,
                                            CC, CC, TVc, (long)CTVc, (long)CTVc, (long)CTVc);

    // ===== temporal (batch 8) =====
    gemm_tc<3, 1><<<dim3(PT, 3, NB), 256>>>(wtInt, ps, pqk, peT, nullptr, nullptr, nullptr,
                                            QKCc, CC, TVc, (long)CTVc, (long)QKCc * TVc, 0);
    attt_tc<<<dim3(7, 7, NB * SS), 256>>>(alphat, att0t);
    tr_vmajor_kernel<<<dim3(13, CC, NB), 256>>>(ps, psT);
    transpose_b<<<dim3(13, 8, NB * VV), 256>>>(psT, psTk, CC, TT, (long)CC * TT, (long)CC * TT);
    ztemp_tc<<<dim3(PQ, 2, NB * SS * VV), 256>>>();
    gemm_tc<1, 1><<<dim3(PQ, 2, NB * VV), 256>>>(wtOutt, pz, phT, psT, outtB, outtG, outtBe,
                                                 CC, SCc, TT, (long)SCc * TT, (long)CC * TT, (long)CC * TT);
    gemm_tc<1, 0><<<dim3(PQ, 2, NB * VV), 256>>>(wtFft, phT, poT, psT, fftB, fftG, fftBe,
                                                 CC, CC, TT, (long)CC * TT, (long)CC * TT, (long)CC * TT);
    store_out_kernel<<<dim3(13, CC, NB), 256>>>(poT, (float*)d_out);
}